// round 4
// baseline (speedup 1.0000x reference)
#include <cuda_runtime.h>
#include <cstdint>

// Problem constants
#define B_   32
#define CIN  1024
#define COUT 512
#define NSP  1568          // T*H*W = 8*14*14
#define NHEAD 8
#define DK   64

// Scratch buffers (device globals: allocation-free contract)
__device__ float g_k[(size_t)B_ * COUT * NSP];
__device__ float g_q[(size_t)B_ * COUT * NSP];
__device__ float g_v[(size_t)B_ * COUT * NSP];
__device__ float g_o[(size_t)B_ * COUT * NSP];

// ---------------------------------------------------------------------------
// TF32 helpers
// ---------------------------------------------------------------------------
__device__ __forceinline__ uint32_t f2tf(float x) {
    uint32_t r;
    asm("cvt.rna.tf32.f32 %0, %1;" : "=r"(r) : "f"(x));
    return r;
}

__device__ __forceinline__ void mma8(float* d, const uint32_t* a, const uint32_t* b) {
    asm volatile(
        "mma.sync.aligned.m16n8k8.row.col.f32.tf32.tf32.f32 "
        "{%0,%1,%2,%3},{%4,%5,%6,%7},{%8,%9},{%0,%1,%2,%3};"
        : "+f"(d[0]), "+f"(d[1]), "+f"(d[2]), "+f"(d[3])
        : "r"(a[0]), "r"(a[1]), "r"(a[2]), "r"(a[3]), "r"(b[0]), "r"(b[1]));
}

// ---------------------------------------------------------------------------
// TF32 tensor-core GEMM body: Y[m,n] = sum_k W[m,k] * X[k,n] + bias[m]
// BM=256, BN=128, BK=16, 256 threads (8 warps, 4x2), warp tile 64x64.
// Double-buffered dynamic smem, one __syncthreads per K-step.
// k-permutation: frag-col c <-> k=2c, c+4 <-> 2c+1 (A and B both) => exact.
// M % 256 == 0, K % 16 == 0 assumed. N guarded (N % 4 == 0).
// ---------------------------------------------------------------------------
#define AST 24    // As row stride (words)
#define BST 132   // Bs row stride (words)
#define A_STAGE_W (256 * AST)          // 6144 words
#define B_STAGE_W (16 * BST)           // 2112 words
#define GEMM_SMEM_BYTES ((2 * A_STAGE_W + 2 * B_STAGE_W) * 4)   // 66048 B

__device__ __forceinline__ void gemm_body(
    const float* __restrict__ W, const float* __restrict__ X,
    const float* __restrict__ bias, float* __restrict__ Y,
    int M, int N, int K, int m0, int n0, uint32_t* smem)
{
    uint32_t* Asm = smem;                      // [2][256][AST]
    uint32_t* Bsm = smem + 2 * A_STAGE_W;      // [2][16][BST]

    const int tid  = threadIdx.x;
    const int lane = tid & 31;
    const int wid  = tid >> 5;
    const int g    = lane >> 2;     // 0..7
    const int c    = lane & 3;      // 0..3
    const int wm   = (wid & 3) * 64;    // 0/64/128/192
    const int wn   = (wid >> 2) * 64;   // 0/64

    // A LDG mapping: rows rowA + 64a (a=0..3), k chunk kqA
    const int rowA = tid >> 2;          // 0..63
    const int kqA  = (tid & 3) << 2;    // 0,4,8,12
    // B LDG mapping: rows kB, kB+8 ; cols nB..nB+3
    const int kB = tid >> 5;            // 0..7
    const int nB = (tid & 31) << 2;     // 0..124
    const bool bval = (n0 + nB) < N;

    const float* Ap[4];
#pragma unroll
    for (int a = 0; a < 4; a++)
        Ap[a] = W + (size_t)(m0 + rowA + 64 * a) * K + kqA;
    const float* Bp0 = X + (size_t)kB * N + n0 + nB;
    const float* Bp1 = Bp0 + (size_t)8 * N;

    float acc[4][8][4];
#pragma unroll
    for (int mt = 0; mt < 4; mt++)
#pragma unroll
        for (int nt = 0; nt < 8; nt++)
#pragma unroll
            for (int r = 0; r < 4; r++) acc[mt][nt][r] = 0.f;

    const int KT = K >> 4;
    const float4 fz = make_float4(0.f, 0.f, 0.f, 0.f);
    float4 ra[4], rb0, rb1;

    // preload tile 0
#pragma unroll
    for (int a = 0; a < 4; a++) ra[a] = *(const float4*)(Ap[a]);
    rb0 = bval ? *(const float4*)(Bp0) : fz;
    rb1 = bval ? *(const float4*)(Bp1) : fz;

    // STS tile 0 -> buffer 0
    {
        uint32_t* A0 = Asm;
#pragma unroll
        for (int a = 0; a < 4; a++) {
            uint4 u;
            u.x = f2tf(ra[a].x); u.y = f2tf(ra[a].y);
            u.z = f2tf(ra[a].z); u.w = f2tf(ra[a].w);
            *(uint4*)&A0[(rowA + 64 * a) * AST + kqA] = u;
        }
        uint4 u;
        u.x = f2tf(rb0.x); u.y = f2tf(rb0.y); u.z = f2tf(rb0.z); u.w = f2tf(rb0.w);
        *(uint4*)&Bsm[kB * BST + nB] = u;
        u.x = f2tf(rb1.x); u.y = f2tf(rb1.y); u.z = f2tf(rb1.z); u.w = f2tf(rb1.w);
        *(uint4*)&Bsm[(kB + 8) * BST + nB] = u;
    }
    __syncthreads();

    for (int kt = 0; kt < KT; kt++) {
        const int cur = kt & 1;
        uint32_t* Ac = Asm + cur * A_STAGE_W;
        uint32_t* Bc = Bsm + cur * B_STAGE_W;

        if (kt + 1 < KT) {
            const int k0 = (kt + 1) << 4;
#pragma unroll
            for (int a = 0; a < 4; a++) ra[a] = *(const float4*)(Ap[a] + k0);
            rb0 = bval ? *(const float4*)(Bp0 + (size_t)k0 * N) : fz;
            rb1 = bval ? *(const float4*)(Bp1 + (size_t)k0 * N) : fz;
        }

#pragma unroll
        for (int ks = 0; ks < 16; ks += 8) {
            uint32_t af[4][4];
#pragma unroll
            for (int mt = 0; mt < 4; mt++) {
                uint2 lo = *(const uint2*)&Ac[(wm + mt * 16 + g) * AST + ks + 2 * c];
                uint2 hi = *(const uint2*)&Ac[(wm + mt * 16 + 8 + g) * AST + ks + 2 * c];
                af[mt][0] = lo.x; af[mt][2] = lo.y;
                af[mt][1] = hi.x; af[mt][3] = hi.y;
            }
            uint32_t bf[8][2];
#pragma unroll
            for (int nt = 0; nt < 8; nt++) {
                bf[nt][0] = Bc[(ks + 2 * c) * BST + wn + nt * 8 + g];
                bf[nt][1] = Bc[(ks + 2 * c + 1) * BST + wn + nt * 8 + g];
            }
#pragma unroll
            for (int mt = 0; mt < 4; mt++)
#pragma unroll
                for (int nt = 0; nt < 8; nt++)
                    mma8(acc[mt][nt], af[mt], bf[nt]);
        }

        if (kt + 1 < KT) {
            const int nxt = cur ^ 1;
            uint32_t* An = Asm + nxt * A_STAGE_W;
            uint32_t* Bn = Bsm + nxt * B_STAGE_W;
#pragma unroll
            for (int a = 0; a < 4; a++) {
                uint4 u;
                u.x = f2tf(ra[a].x); u.y = f2tf(ra[a].y);
                u.z = f2tf(ra[a].z); u.w = f2tf(ra[a].w);
                *(uint4*)&An[(rowA + 64 * a) * AST + kqA] = u;
            }
            uint4 u;
            u.x = f2tf(rb0.x); u.y = f2tf(rb0.y); u.z = f2tf(rb0.z); u.w = f2tf(rb0.w);
            *(uint4*)&Bn[kB * BST + nB] = u;
            u.x = f2tf(rb1.x); u.y = f2tf(rb1.y); u.z = f2tf(rb1.z); u.w = f2tf(rb1.w);
            *(uint4*)&Bn[(kB + 8) * BST + nB] = u;
            __syncthreads();
        }
    }

    // Epilogue: bias + guarded float2 stores
#pragma unroll
    for (int mt = 0; mt < 4; mt++) {
        const int mA = m0 + wm + mt * 16 + g;
        const float bb0 = bias[mA];
        const float bb1 = bias[mA + 8];
#pragma unroll
        for (int nt = 0; nt < 8; nt++) {
            const int n = n0 + wn + nt * 8 + 2 * c;
            if (n < N) {
                float2 o0, o1;
                o0.x = acc[mt][nt][0] + bb0; o0.y = acc[mt][nt][1] + bb0;
                o1.x = acc[mt][nt][2] + bb1; o1.y = acc[mt][nt][3] + bb1;
                *(float2*)&Y[(size_t)mA * N + n]       = o0;
                *(float2*)&Y[(size_t)(mA + 8) * N + n] = o1;
            }
        }
    }
}

// ---------------------------------------------------------------------------
// Fused 3-projection launch: blockIdx.z encodes (proj, batch)
// ---------------------------------------------------------------------------
struct ProjArgs {
    const float* W[3];
    const float* X[3];
    const float* bias[3];
    float*       Y[3];
};

__global__ void __launch_bounds__(256, 1)
proj3_kernel(ProjArgs pa)
{
    extern __shared__ uint32_t smem[];
    const int which = blockIdx.z % 3;
    const int b     = blockIdx.z / 3;
    const float* W    = pa.W[which];
    const float* X    = pa.X[which] + (size_t)b * CIN * NSP;
    const float* bias = pa.bias[which];
    float*       Y    = pa.Y[which] + (size_t)b * COUT * NSP;
    gemm_body(W, X, bias, Y, COUT, NSP, CIN,
              blockIdx.y * 256, blockIdx.x * 128, smem);
}

__global__ void __launch_bounds__(256, 1)
up_kernel(const float* __restrict__ W, const float* __restrict__ X,
          const float* __restrict__ bias, float* __restrict__ Y)
{
    extern __shared__ uint32_t smem[];
    const int b = blockIdx.z;
    gemm_body(W, X + (size_t)b * COUT * NSP, bias, Y + (size_t)b * CIN * NSP,
              CIN, NSP, COUT, blockIdx.y * 256, blockIdx.x * 128, smem);
}

// ---------------------------------------------------------------------------
// Attention per (b, h) — unchanged (fp32 SIMT, ~300us total).
// ---------------------------------------------------------------------------
__global__ void __launch_bounds__(256)
attention_kernel(const float* __restrict__ Kp, const float* __restrict__ Qp,
                 const float* __restrict__ Vp, float* __restrict__ Op)
{
    const int bh = blockIdx.x;
    const int b = bh >> 3;
    const int h = bh & 7;
    const size_t base = (size_t)b * (COUT * NSP);

    const float* Kb = Kp + base + h * DK;
    const float* Qb = Qp + base + h * DK;
    const float* Vb = Vp + base + h * DK;
    float*       Ob = Op + base;

    __shared__ float Ks[32][65];
    __shared__ float Qs[32][65];
    __shared__ float Vs[32][65];
    __shared__ float Ss[64][65];

    const int tid = threadIdx.x;
    const int tx = tid & 15;
    const int ty = tid >> 4;

    float acc[4][4];
#pragma unroll
    for (int i = 0; i < 4; i++)
#pragma unroll
        for (int j = 0; j < 4; j++) acc[i][j] = 0.f;

    for (int nb = 0; nb < NSP; nb += 32) {
#pragma unroll
        for (int u = 0; u < 2; u++) {
            const int idx = tid + u * 256;
            const int r = idx >> 4;
            const int cc = (idx & 15) << 2;
            const size_t gg = (size_t)(nb + r) * COUT + cc;
            float4 kv = *(const float4*)&Kb[gg];
            Ks[r][cc + 0] = kv.x; Ks[r][cc + 1] = kv.y;
            Ks[r][cc + 2] = kv.z; Ks[r][cc + 3] = kv.w;
            float4 qv = *(const float4*)&Qb[gg];
            Qs[r][cc + 0] = qv.x; Qs[r][cc + 1] = qv.y;
            Qs[r][cc + 2] = qv.z; Qs[r][cc + 3] = qv.w;
        }
        __syncthreads();
#pragma unroll
        for (int n = 0; n < 32; n++) {
            float ar[4], br[4];
#pragma unroll
            for (int i = 0; i < 4; i++) ar[i] = Ks[n][ty * 4 + i];
#pragma unroll
            for (int j = 0; j < 4; j++) br[j] = Qs[n][tx * 4 + j];
#pragma unroll
            for (int i = 0; i < 4; i++)
#pragma unroll
                for (int j = 0; j < 4; j++)
                    acc[i][j] += ar[i] * br[j];
        }
        __syncthreads();
    }

#pragma unroll
    for (int i = 0; i < 4; i++)
#pragma unroll
        for (int j = 0; j < 4; j++)
            Ss[ty * 4 + i][tx * 4 + j] = acc[i][j] * 0.125f;
    __syncthreads();

    if (tid < 64) {
        float mx = -1e30f;
#pragma unroll 8
        for (int j = 0; j < 64; j++) mx = fmaxf(mx, Ss[tid][j]);
        float sum = 0.f;
#pragma unroll 8
        for (int j = 0; j < 64; j++) {
            float e = expf(Ss[tid][j] - mx);
            Ss[tid][j] = e;
            sum += e;
        }
        const float inv = 1.0f / sum;
#pragma unroll 8
        for (int j = 0; j < 64; j++) Ss[tid][j] *= inv;
    }
    __syncthreads();

    for (int nb = 0; nb < NSP; nb += 32) {
#pragma unroll
        for (int u = 0; u < 2; u++) {
            const int idx = tid + u * 256;
            const int r = idx >> 4;
            const int cc = (idx & 15) << 2;
            float4 vv = *(const float4*)&Vb[(size_t)(nb + r) * COUT + cc];
            Vs[r][cc + 0] = vv.x; Vs[r][cc + 1] = vv.y;
            Vs[r][cc + 2] = vv.z; Vs[r][cc + 3] = vv.w;
        }
        __syncthreads();

        float o[4][2];
#pragma unroll
        for (int i = 0; i < 4; i++) { o[i][0] = 0.f; o[i][1] = 0.f; }
#pragma unroll
        for (int j = 0; j < 64; j++) {
            const float v0 = Vs[tx][j];
            const float v1 = Vs[16 + tx][j];
#pragma unroll
            for (int i = 0; i < 4; i++) {
                const float p = Ss[ty * 4 + i][j];
                o[i][0] += p * v0;
                o[i][1] += p * v1;
            }
        }
#pragma unroll
        for (int i = 0; i < 4; i++) {
            const int o2 = (ty * 4 + i) * NHEAD + h;
            Ob[(size_t)o2 * NSP + nb + tx]      = o[i][0];
            Ob[(size_t)o2 * NSP + nb + 16 + tx] = o[i][1];
        }
        __syncthreads();
    }
}

// ---------------------------------------------------------------------------
// Launch
// ---------------------------------------------------------------------------
extern "C" void kernel_launch(void* const* d_in, const int* in_sizes, int n_in,
                              void* d_out, int out_size)
{
    const float* x       = (const float*)d_in[0];
    const float* query   = (const float*)d_in[1];
    const float* key_w   = (const float*)d_in[2];
    const float* key_b   = (const float*)d_in[3];
    const float* query_w = (const float*)d_in[4];
    const float* query_b = (const float*)d_in[5];
    const float* val_w   = (const float*)d_in[6];
    const float* val_b   = (const float*)d_in[7];
    const float* up_w    = (const float*)d_in[8];
    const float* up_b    = (const float*)d_in[9];
    float* out = (float*)d_out;

    float *kbuf, *qbuf, *vbuf, *obuf;
    cudaGetSymbolAddress((void**)&kbuf, g_k);
    cudaGetSymbolAddress((void**)&qbuf, g_q);
    cudaGetSymbolAddress((void**)&vbuf, g_v);
    cudaGetSymbolAddress((void**)&obuf, g_o);

    cudaFuncSetAttribute(proj3_kernel,
                         cudaFuncAttributeMaxDynamicSharedMemorySize, GEMM_SMEM_BYTES);
    cudaFuncSetAttribute(up_kernel,
                         cudaFuncAttributeMaxDynamicSharedMemorySize, GEMM_SMEM_BYTES);

    ProjArgs pa;
    pa.W[0] = key_w;   pa.W[1] = query_w; pa.W[2] = val_w;
    pa.X[0] = x;       pa.X[1] = query;   pa.X[2] = x;
    pa.bias[0] = key_b; pa.bias[1] = query_b; pa.bias[2] = val_b;
    pa.Y[0] = kbuf;    pa.Y[1] = qbuf;    pa.Y[2] = vbuf;

    const dim3 blk(256);
    const dim3 grid_proj((NSP + 127) / 128, COUT / 256, 3 * B_);   // (13, 2, 96)
    const dim3 grid_up((NSP + 127) / 128, CIN / 256, B_);          // (13, 4, 32)

    proj3_kernel<<<grid_proj, blk, GEMM_SMEM_BYTES>>>(pa);
    attention_kernel<<<B_ * NHEAD, blk>>>(kbuf, qbuf, vbuf, obuf);
    up_kernel<<<grid_up, blk, GEMM_SMEM_BYTES>>>(up_w, obuf, up_b, out);
}

// round 5
// speedup vs baseline: 1.1373x; 1.1373x over previous
#include <cuda_runtime.h>
#include <cuda_fp16.h>
#include <cstdint>

// Problem constants
#define B_   32
#define CIN  1024
#define COUT 512
#define NSP  1568          // T*H*W = 8*14*14
#define NHEAD 8
#define DK   64

// Scratch buffers (device globals: allocation-free contract)
__device__ float g_k[(size_t)B_ * COUT * NSP];
__device__ float g_q[(size_t)B_ * COUT * NSP];
__device__ float g_v[(size_t)B_ * COUT * NSP];
__device__ float g_o[(size_t)B_ * COUT * NSP];

// ---------------------------------------------------------------------------
// FP16 helpers
// ---------------------------------------------------------------------------
__device__ __forceinline__ uint32_t pk(float lo, float hi) {
    __half2 h = __floats2half2_rn(lo, hi);   // x = lo, y = hi (memory order lo,hi)
    return *reinterpret_cast<uint32_t*>(&h);
}

__device__ __forceinline__ void mma16(float* d, const uint32_t* a, const uint32_t* b) {
    asm volatile(
        "mma.sync.aligned.m16n8k16.row.col.f32.f16.f16.f32 "
        "{%0,%1,%2,%3},{%4,%5,%6,%7},{%8,%9},{%0,%1,%2,%3};"
        : "+f"(d[0]), "+f"(d[1]), "+f"(d[2]), "+f"(d[3])
        : "r"(a[0]), "r"(a[1]), "r"(a[2]), "r"(a[3]), "r"(b[0]), "r"(b[1]));
}

// ---------------------------------------------------------------------------
// FP16 tensor-core GEMM body: Y[m,n] = sum_k W[m,k] * X[k,n] + bias[m]
// BM=BN=128, BK=32, 512 threads (16 warps, 4x4), warp tile 32x32.
// Double-buffered smem of halves, row stride 48 halves (96B): fragment
// LDS.64 loads are conflict-free (24g mod 32 in {0,24,16,8} per phase).
// k-permutation within each k16: spec {2c,2c+1,2c+8,2c+9} -> actual
// {4c,4c+1,4c+2,4c+3}, applied to BOTH A and B => numerically exact.
// B is transposed gmem[k][n] -> smem[n][k] via coalesced column LDG.32.
// M % 128 == 0, K % 32 == 0 assumed. N guarded (N % 4 == 0).
// ---------------------------------------------------------------------------
#define HST 48                 // smem row stride in halves
#define ABUF (128 * HST)       // 6144 halves per buffer per array
#define GEMM_SMEM_BYTES (4 * ABUF * 2)   // A[2] + B[2] = 49152 B

__device__ __forceinline__ void gemm_body(
    const float* __restrict__ W, const float* __restrict__ X,
    const float* __restrict__ bias, float* __restrict__ Y,
    int M, int N, int K, int m0, int n0, uint16_t* hsm)
{
    uint16_t* Ah = hsm;                 // [2][128][HST]
    uint16_t* Bh = hsm + 2 * ABUF;      // [2][128][HST]

    const int tid  = threadIdx.x;
    const int lane = tid & 31;
    const int w    = tid >> 5;          // 0..15
    const int g    = lane >> 2;         // 0..7
    const int c    = lane & 3;          // 0..3
    const int wm   = (w & 3) << 5;      // 0/32/64/96
    const int wn   = (w >> 2) << 5;     // 0/32/64/96

    // A gmem mapping: m row, 8 consecutive k
    const int mA = tid >> 2;            // 0..127
    const int kA = (tid & 3) << 3;      // 0,8,16,24
    const float* pA = W + (size_t)(m0 + mA) * K + kA;

    // B gmem mapping: column n, 8 consecutive k
    const int nB  = tid & 127;          // 0..127
    const int kB  = (tid >> 7) << 3;    // 0,8,16,24
    const bool bval = (n0 + nB) < N;
    const float* pB = X + n0 + nB;

    float acc[2][4][4];
#pragma unroll
    for (int mt = 0; mt < 2; mt++)
#pragma unroll
        for (int nt = 0; nt < 4; nt++)
#pragma unroll
            for (int r = 0; r < 4; r++) acc[mt][nt][r] = 0.f;

    const int KT = K >> 5;

    float4 ra0, ra1;
    float  rb[8];

    // ---- prologue: load tile 0 ----
    ra0 = *(const float4*)(pA);
    ra1 = *(const float4*)(pA + 4);
#pragma unroll
    for (int j = 0; j < 8; j++)
        rb[j] = bval ? pB[(size_t)(kB + j) * N] : 0.f;

    {
        uint4 ua;
        ua.x = pk(ra0.x, ra0.y); ua.y = pk(ra0.z, ra0.w);
        ua.z = pk(ra1.x, ra1.y); ua.w = pk(ra1.z, ra1.w);
        *(uint4*)&Ah[mA * HST + kA] = ua;
        uint4 ub;
        ub.x = pk(rb[0], rb[1]); ub.y = pk(rb[2], rb[3]);
        ub.z = pk(rb[4], rb[5]); ub.w = pk(rb[6], rb[7]);
        *(uint4*)&Bh[nB * HST + kB] = ub;
    }
    __syncthreads();

    for (int kt = 0; kt < KT; kt++) {
        const int cur = kt & 1;
        uint16_t* Ac = Ah + cur * ABUF;
        uint16_t* Bc = Bh + cur * ABUF;

        if (kt + 1 < KT) {
            const int k0 = (kt + 1) << 5;
            ra0 = *(const float4*)(pA + k0);
            ra1 = *(const float4*)(pA + k0 + 4);
#pragma unroll
            for (int j = 0; j < 8; j++)
                rb[j] = bval ? pB[(size_t)(k0 + kB + j) * N] : 0.f;
        }

#pragma unroll
        for (int ks = 0; ks < 2; ks++) {
            const int ko = ks * 16 + 4 * c;
            uint32_t af[2][4];
#pragma unroll
            for (int mt = 0; mt < 2; mt++) {
                uint2 ua = *(const uint2*)&Ac[(wm + mt * 16 + g) * HST + ko];
                uint2 ub = *(const uint2*)&Ac[(wm + mt * 16 + 8 + g) * HST + ko];
                af[mt][0] = ua.x; af[mt][2] = ua.y;   // row g:   k 4c..4c+3
                af[mt][1] = ub.x; af[mt][3] = ub.y;   // row g+8
            }
            uint32_t bf[4][2];
#pragma unroll
            for (int nt = 0; nt < 4; nt++) {
                uint2 vb = *(const uint2*)&Bc[(wn + nt * 8 + g) * HST + ko];
                bf[nt][0] = vb.x; bf[nt][1] = vb.y;
            }
#pragma unroll
            for (int mt = 0; mt < 2; mt++)
#pragma unroll
                for (int nt = 0; nt < 4; nt++)
                    mma16(acc[mt][nt], af[mt], bf[nt]);
        }

        if (kt + 1 < KT) {
            const int nxt = cur ^ 1;
            uint16_t* An = Ah + nxt * ABUF;
            uint16_t* Bn = Bh + nxt * ABUF;
            uint4 ua;
            ua.x = pk(ra0.x, ra0.y); ua.y = pk(ra0.z, ra0.w);
            ua.z = pk(ra1.x, ra1.y); ua.w = pk(ra1.z, ra1.w);
            *(uint4*)&An[mA * HST + kA] = ua;
            uint4 ub;
            ub.x = pk(rb[0], rb[1]); ub.y = pk(rb[2], rb[3]);
            ub.z = pk(rb[4], rb[5]); ub.w = pk(rb[6], rb[7]);
            *(uint4*)&Bn[nB * HST + kB] = ub;
            __syncthreads();
        }
    }

    // ---- epilogue: bias + guarded float2 stores ----
#pragma unroll
    for (int mt = 0; mt < 2; mt++) {
        const int mrow = m0 + wm + mt * 16 + g;
        const float bb0 = bias[mrow];
        const float bb1 = bias[mrow + 8];
#pragma unroll
        for (int nt = 0; nt < 4; nt++) {
            const int n = n0 + wn + nt * 8 + 2 * c;
            if (n < N) {
                float2 o0, o1;
                o0.x = acc[mt][nt][0] + bb0; o0.y = acc[mt][nt][1] + bb0;
                o1.x = acc[mt][nt][2] + bb1; o1.y = acc[mt][nt][3] + bb1;
                *(float2*)&Y[(size_t)mrow * N + n]       = o0;
                *(float2*)&Y[(size_t)(mrow + 8) * N + n] = o1;
            }
        }
    }
}

// ---------------------------------------------------------------------------
// Fused 3-projection launch: blockIdx.z encodes (proj, batch)
// ---------------------------------------------------------------------------
struct ProjArgs {
    const float* W[3];
    const float* X[3];
    const float* bias[3];
    float*       Y[3];
};

__global__ void __launch_bounds__(512, 1)
proj3_kernel(ProjArgs pa)
{
    extern __shared__ uint16_t hsm[];
    const int which = blockIdx.z % 3;
    const int b     = blockIdx.z / 3;
    gemm_body(pa.W[which], pa.X[which] + (size_t)b * CIN * NSP,
              pa.bias[which], pa.Y[which] + (size_t)b * COUT * NSP,
              COUT, NSP, CIN, blockIdx.y * 128, blockIdx.x * 128, hsm);
}

__global__ void __launch_bounds__(512, 1)
up_kernel(const float* __restrict__ W, const float* __restrict__ X,
          const float* __restrict__ bias, float* __restrict__ Y)
{
    extern __shared__ uint16_t hsm[];
    const int b = blockIdx.z;
    gemm_body(W, X + (size_t)b * COUT * NSP, bias, Y + (size_t)b * CIN * NSP,
              CIN, NSP, COUT, blockIdx.y * 128, blockIdx.x * 128, hsm);
}

// ---------------------------------------------------------------------------
// Attention per (b, h) — unchanged (fp32 SIMT, ~300us total).
// ---------------------------------------------------------------------------
__global__ void __launch_bounds__(256)
attention_kernel(const float* __restrict__ Kp, const float* __restrict__ Qp,
                 const float* __restrict__ Vp, float* __restrict__ Op)
{
    const int bh = blockIdx.x;
    const int b = bh >> 3;
    const int h = bh & 7;
    const size_t base = (size_t)b * (COUT * NSP);

    const float* Kb = Kp + base + h * DK;
    const float* Qb = Qp + base + h * DK;
    const float* Vb = Vp + base + h * DK;
    float*       Ob = Op + base;

    __shared__ float Ks[32][65];
    __shared__ float Qs[32][65];
    __shared__ float Vs[32][65];
    __shared__ float Ss[64][65];

    const int tid = threadIdx.x;
    const int tx = tid & 15;
    const int ty = tid >> 4;

    float acc[4][4];
#pragma unroll
    for (int i = 0; i < 4; i++)
#pragma unroll
        for (int j = 0; j < 4; j++) acc[i][j] = 0.f;

    for (int nb = 0; nb < NSP; nb += 32) {
#pragma unroll
        for (int u = 0; u < 2; u++) {
            const int idx = tid + u * 256;
            const int r = idx >> 4;
            const int cc = (idx & 15) << 2;
            const size_t gg = (size_t)(nb + r) * COUT + cc;
            float4 kv = *(const float4*)&Kb[gg];
            Ks[r][cc + 0] = kv.x; Ks[r][cc + 1] = kv.y;
            Ks[r][cc + 2] = kv.z; Ks[r][cc + 3] = kv.w;
            float4 qv = *(const float4*)&Qb[gg];
            Qs[r][cc + 0] = qv.x; Qs[r][cc + 1] = qv.y;
            Qs[r][cc + 2] = qv.z; Qs[r][cc + 3] = qv.w;
        }
        __syncthreads();
#pragma unroll
        for (int n = 0; n < 32; n++) {
            float ar[4], br[4];
#pragma unroll
            for (int i = 0; i < 4; i++) ar[i] = Ks[n][ty * 4 + i];
#pragma unroll
            for (int j = 0; j < 4; j++) br[j] = Qs[n][tx * 4 + j];
#pragma unroll
            for (int i = 0; i < 4; i++)
#pragma unroll
                for (int j = 0; j < 4; j++)
                    acc[i][j] += ar[i] * br[j];
        }
        __syncthreads();
    }

#pragma unroll
    for (int i = 0; i < 4; i++)
#pragma unroll
        for (int j = 0; j < 4; j++)
            Ss[ty * 4 + i][tx * 4 + j] = acc[i][j] * 0.125f;
    __syncthreads();

    if (tid < 64) {
        float mx = -1e30f;
#pragma unroll 8
        for (int j = 0; j < 64; j++) mx = fmaxf(mx, Ss[tid][j]);
        float sum = 0.f;
#pragma unroll 8
        for (int j = 0; j < 64; j++) {
            float e = expf(Ss[tid][j] - mx);
            Ss[tid][j] = e;
            sum += e;
        }
        const float inv = 1.0f / sum;
#pragma unroll 8
        for (int j = 0; j < 64; j++) Ss[tid][j] *= inv;
    }
    __syncthreads();

    for (int nb = 0; nb < NSP; nb += 32) {
#pragma unroll
        for (int u = 0; u < 2; u++) {
            const int idx = tid + u * 256;
            const int r = idx >> 4;
            const int cc = (idx & 15) << 2;
            float4 vv = *(const float4*)&Vb[(size_t)(nb + r) * COUT + cc];
            Vs[r][cc + 0] = vv.x; Vs[r][cc + 1] = vv.y;
            Vs[r][cc + 2] = vv.z; Vs[r][cc + 3] = vv.w;
        }
        __syncthreads();

        float o[4][2];
#pragma unroll
        for (int i = 0; i < 4; i++) { o[i][0] = 0.f; o[i][1] = 0.f; }
#pragma unroll
        for (int j = 0; j < 64; j++) {
            const float v0 = Vs[tx][j];
            const float v1 = Vs[16 + tx][j];
#pragma unroll
            for (int i = 0; i < 4; i++) {
                const float p = Ss[ty * 4 + i][j];
                o[i][0] += p * v0;
                o[i][1] += p * v1;
            }
        }
#pragma unroll
        for (int i = 0; i < 4; i++) {
            const int o2 = (ty * 4 + i) * NHEAD + h;
            Ob[(size_t)o2 * NSP + nb + tx]      = o[i][0];
            Ob[(size_t)o2 * NSP + nb + 16 + tx] = o[i][1];
        }
        __syncthreads();
    }
}

// ---------------------------------------------------------------------------
// Launch
// ---------------------------------------------------------------------------
extern "C" void kernel_launch(void* const* d_in, const int* in_sizes, int n_in,
                              void* d_out, int out_size)
{
    const float* x       = (const float*)d_in[0];
    const float* query   = (const float*)d_in[1];
    const float* key_w   = (const float*)d_in[2];
    const float* key_b   = (const float*)d_in[3];
    const float* query_w = (const float*)d_in[4];
    const float* query_b = (const float*)d_in[5];
    const float* val_w   = (const float*)d_in[6];
    const float* val_b   = (const float*)d_in[7];
    const float* up_w    = (const float*)d_in[8];
    const float* up_b    = (const float*)d_in[9];
    float* out = (float*)d_out;

    float *kbuf, *qbuf, *vbuf, *obuf;
    cudaGetSymbolAddress((void**)&kbuf, g_k);
    cudaGetSymbolAddress((void**)&qbuf, g_q);
    cudaGetSymbolAddress((void**)&vbuf, g_v);
    cudaGetSymbolAddress((void**)&obuf, g_o);

    cudaFuncSetAttribute(proj3_kernel,
                         cudaFuncAttributeMaxDynamicSharedMemorySize, GEMM_SMEM_BYTES);
    cudaFuncSetAttribute(up_kernel,
                         cudaFuncAttributeMaxDynamicSharedMemorySize, GEMM_SMEM_BYTES);

    ProjArgs pa;
    pa.W[0] = key_w;    pa.W[1] = query_w;    pa.W[2] = val_w;
    pa.X[0] = x;        pa.X[1] = query;      pa.X[2] = x;
    pa.bias[0] = key_b; pa.bias[1] = query_b; pa.bias[2] = val_b;
    pa.Y[0] = kbuf;     pa.Y[1] = qbuf;       pa.Y[2] = vbuf;

    const dim3 blk(512);
    const dim3 grid_proj((NSP + 127) / 128, COUT / 128, 3 * B_);   // (13, 4, 96)
    const dim3 grid_up((NSP + 127) / 128, CIN / 128, B_);          // (13, 8, 32)

    proj3_kernel<<<grid_proj, blk, GEMM_SMEM_BYTES>>>(pa);
    attention_kernel<<<B_ * NHEAD, dim3(256)>>>(kbuf, qbuf, vbuf, obuf);
    up_kernel<<<grid_up, blk, GEMM_SMEM_BYTES>>>(up_w, obuf, up_b, out);
}